// round 1
// baseline (speedup 1.0000x reference)
#include <cuda_runtime.h>
#include <cstdint>

// Problem constants
#define BB 8
#define SS 2048
#define EE 1024
#define HH 64
#define BSROWS (BB*SS)   // 16384

// ---------------- scratch (device globals; no allocation allowed) ----------
__device__ float g_Q[BB*SS*HH];
__device__ float g_K[BB*SS*HH];
__device__ float g_V[BB*SS*HH];
__device__ int   g_mask_mode;   // 0 = int32, 1 = uint8/bool, 2 = float32

// ---------------- mask dtype detection -------------------------------------
// jax bool may arrive as 1-byte bool, promoted int32, or float32. Classify by
// inspecting the first 256 32-bit words (mask buffer is >= 33 MB, safe).
__global__ void detect_mask_kernel(const unsigned int* __restrict__ m) {
    if (threadIdx.x == 0 && blockIdx.x == 0) {
        bool all_01 = true;      // int32 with values {0,1}
        bool all_f  = true;      // float32 with values {0.0f,1.0f}
        for (int i = 0; i < 256; i++) {
            unsigned v = m[i];
            if (v > 1u) all_01 = false;
            if (v != 0u && v != 0x3F800000u) all_f = false;
        }
        g_mask_mode = all_01 ? 0 : (all_f ? 2 : 1);
    }
}

// ---------------- fused QKV projection -------------------------------------
// C[M=16384, N=64] = A[M,1024] @ W[1024,64] + bias.  blockIdx.y selects Q/K/V.
// 64x64 output tile per block, K-tiles of 32, 4x4 register microtile / thread.
__global__ __launch_bounds__(256) void proj_kernel(
    const float* __restrict__ A0, const float* __restrict__ A1, const float* __restrict__ A2,
    const float* __restrict__ W0, const float* __restrict__ W1, const float* __restrict__ W2,
    const float* __restrict__ b0, const float* __restrict__ b1, const float* __restrict__ b2)
{
    const float *A, *W, *bias; float* C;
    if (blockIdx.y == 0)      { A = A0; W = W0; bias = b0; C = g_Q; }
    else if (blockIdx.y == 1) { A = A1; W = W1; bias = b1; C = g_K; }
    else                      { A = A2; W = W2; bias = b2; C = g_V; }

    __shared__ float As[32][65];   // A tile transposed: As[k][m]
    __shared__ float Ws[32][64];   // W tile:            Ws[k][n]

    const int tid = threadIdx.x;
    const int tx  = tid & 15;      // 16 col-groups (n)
    const int ty  = tid >> 4;      // 16 row-groups (m)
    const int row0 = blockIdx.x * 64;

    float acc[4][4] = {};

    for (int k0 = 0; k0 < EE; k0 += 32) {
        #pragma unroll
        for (int i = 0; i < 8; i++) {              // 2048 elems of A
            int idx = tid + i * 256;
            int m = idx >> 5, k = idx & 31;
            As[k][m] = A[(size_t)(row0 + m) * EE + k0 + k];
        }
        #pragma unroll
        for (int i = 0; i < 8; i++) {              // 2048 elems of W
            int idx = tid + i * 256;
            int k = idx >> 6, n = idx & 63;
            Ws[k][n] = W[(size_t)(k0 + k) * HH + n];
        }
        __syncthreads();

        #pragma unroll
        for (int k = 0; k < 32; k++) {
            float a[4], w[4];
            #pragma unroll
            for (int i = 0; i < 4; i++) a[i] = As[k][ty * 4 + i];
            #pragma unroll
            for (int j = 0; j < 4; j++) w[j] = Ws[k][tx * 4 + j];
            #pragma unroll
            for (int i = 0; i < 4; i++)
                #pragma unroll
                for (int j = 0; j < 4; j++)
                    acc[i][j] += a[i] * w[j];
        }
        __syncthreads();
    }

    #pragma unroll
    for (int i = 0; i < 4; i++) {
        int m = row0 + ty * 4 + i;
        #pragma unroll
        for (int j = 0; j < 4; j++) {
            int n = tx * 4 + j;
            C[(size_t)m * HH + n] = acc[i][j] + bias[n];
        }
    }
}

// ---------------- flash attention ------------------------------------------
// Per block: one (batch, 64-query) tile. Stream over 32 key tiles of 64.
// Online softmax with reference semantics: masked scores = 1e-10 (NOT -inf),
// included in the softmax.
struct AttnSmem {
    float Qs[64][65];   // Qs[m][h]
    float Ks[64][65];   // Ks[h][n]  (K transposed on load)
    float Ps[64][65];   // Ps[m][n]  probabilities (unnormalized)
    float Vs[64][64];   // Vs[k][h]
    float red[16][65];  // red[tx][row] partial max / sum
    float m_s[64];
    float l_s[64];
    float alpha_s[64];
};

__global__ __launch_bounds__(256) void attn_kernel(
    const void* __restrict__ mask, float* __restrict__ Out)
{
    extern __shared__ char smem_raw[];
    AttnSmem& sm = *reinterpret_cast<AttnSmem*>(smem_raw);

    const int b   = blockIdx.y;
    const int q0  = blockIdx.x * 64;
    const int tid = threadIdx.x;
    const int tx  = tid & 15;   // H columns (4 each)
    const int ty  = tid >> 4;   // query rows (4 each)

    const float* Q = g_Q + (size_t)b * SS * HH;
    const float* K = g_K + (size_t)b * SS * HH;
    const float* V = g_V + (size_t)b * SS * HH;
    const int mmode = g_mask_mode;

    // load Q tile [64 rows][64 h]
    #pragma unroll
    for (int i = 0; i < 16; i++) {
        int idx = tid + i * 256;
        int m = idx >> 6, h = idx & 63;
        sm.Qs[m][h] = Q[(size_t)(q0 + m) * HH + h];
    }
    if (tid < 64) { sm.m_s[tid] = -INFINITY; sm.l_s[tid] = 0.f; }

    float acc[4][4] = {};

    for (int kt = 0; kt < 32; kt++) {
        const int k0 = kt * 64;
        __syncthreads();   // (A) prev GEMM2 done reading Ks/Vs/Ps, red readers done

        #pragma unroll
        for (int i = 0; i < 16; i++) {             // K tile, transposed
            int idx = tid + i * 256;
            int n = idx >> 6, h = idx & 63;
            sm.Ks[h][n] = K[(size_t)(k0 + n) * HH + h];
        }
        #pragma unroll
        for (int i = 0; i < 16; i++) {             // V tile
            int idx = tid + i * 256;
            int k = idx >> 6, h = idx & 63;
            sm.Vs[k][h] = V[(size_t)(k0 + k) * HH + h];
        }
        __syncthreads();   // (B)

        // GEMM1: s[m][n] = sum_h Q[m][h] * K[n][h]
        float s[4][4] = {};
        #pragma unroll
        for (int h = 0; h < 64; h++) {
            float a[4], kk[4];
            #pragma unroll
            for (int i = 0; i < 4; i++) a[i]  = sm.Qs[ty * 4 + i][h];
            #pragma unroll
            for (int j = 0; j < 4; j++) kk[j] = sm.Ks[h][tx * 4 + j];
            #pragma unroll
            for (int i = 0; i < 4; i++)
                #pragma unroll
                for (int j = 0; j < 4; j++)
                    s[i][j] += a[i] * kk[j];
        }

        // scale + masked fill (mask==true -> 1e-10, reference semantics)
        #pragma unroll
        for (int i = 0; i < 4; i++) {
            const size_t eoff = ((size_t)b * SS + (q0 + ty * 4 + i)) * SS + k0 + tx * 4;
            if (mmode == 1) {
                unsigned mv = *reinterpret_cast<const unsigned*>(
                    reinterpret_cast<const unsigned char*>(mask) + eoff);
                #pragma unroll
                for (int j = 0; j < 4; j++) {
                    bool mk = ((mv >> (8 * j)) & 0xFFu) != 0u;
                    s[i][j] = mk ? 1e-10f : s[i][j] * 0.125f;
                }
            } else if (mmode == 0) {
                int4 mv = *reinterpret_cast<const int4*>(
                    reinterpret_cast<const int*>(mask) + eoff);
                int mvv[4] = { mv.x, mv.y, mv.z, mv.w };
                #pragma unroll
                for (int j = 0; j < 4; j++)
                    s[i][j] = (mvv[j] != 0) ? 1e-10f : s[i][j] * 0.125f;
            } else {
                float4 mv = *reinterpret_cast<const float4*>(
                    reinterpret_cast<const float*>(mask) + eoff);
                float mvv[4] = { mv.x, mv.y, mv.z, mv.w };
                #pragma unroll
                for (int j = 0; j < 4; j++)
                    s[i][j] = (mvv[j] != 0.f) ? 1e-10f : s[i][j] * 0.125f;
            }
        }

        // per-row partial max
        #pragma unroll
        for (int i = 0; i < 4; i++) {
            float pm = fmaxf(fmaxf(s[i][0], s[i][1]), fmaxf(s[i][2], s[i][3]));
            sm.red[tx][ty * 4 + i] = pm;
        }
        __syncthreads();   // (C)

        if (tid < 64) {
            float mx = sm.red[0][tid];
            #pragma unroll
            for (int t = 1; t < 16; t++) mx = fmaxf(mx, sm.red[t][tid]);
            float m_old = sm.m_s[tid];
            float m_new = fmaxf(m_old, mx);
            sm.m_s[tid]     = m_new;
            sm.alpha_s[tid] = __expf(m_old - m_new);   // 0 on first tile
        }
        __syncthreads();   // (D)

        // p = exp(s - m_new); write Ps; partial row sums; rescale O acc
        #pragma unroll
        for (int i = 0; i < 4; i++) {
            const int r  = ty * 4 + i;
            const float mn = sm.m_s[r];
            float rs = 0.f;
            #pragma unroll
            for (int j = 0; j < 4; j++) {
                float p = __expf(s[i][j] - mn);
                sm.Ps[r][tx * 4 + j] = p;
                rs += p;
            }
            sm.red[tx][r] = rs;
            const float al = sm.alpha_s[r];
            #pragma unroll
            for (int j = 0; j < 4; j++) acc[i][j] *= al;
        }
        __syncthreads();   // (E)

        if (tid < 64) {
            float ssum = 0.f;
            #pragma unroll
            for (int t = 0; t < 16; t++) ssum += sm.red[t][tid];
            sm.l_s[tid] = sm.l_s[tid] * sm.alpha_s[tid] + ssum;
        }

        // GEMM2: acc[m][h] += sum_k Ps[m][k] * Vs[k][h]
        #pragma unroll
        for (int k = 0; k < 64; k++) {
            float pv[4], vv[4];
            #pragma unroll
            for (int i = 0; i < 4; i++) pv[i] = sm.Ps[ty * 4 + i][k];
            #pragma unroll
            for (int j = 0; j < 4; j++) vv[j] = sm.Vs[k][tx * 4 + j];
            #pragma unroll
            for (int i = 0; i < 4; i++)
                #pragma unroll
                for (int j = 0; j < 4; j++)
                    acc[i][j] += pv[i] * vv[j];
        }
    }
    __syncthreads();  // l_s final

    #pragma unroll
    for (int i = 0; i < 4; i++) {
        const int r = ty * 4 + i;
        const float inv = 1.f / sm.l_s[r];
        #pragma unroll
        for (int j = 0; j < 4; j++)
            Out[((size_t)b * SS + (q0 + r)) * HH + tx * 4 + j] = acc[i][j] * inv;
    }
}

// ---------------- launch ----------------------------------------------------
extern "C" void kernel_launch(void* const* d_in, const int* in_sizes, int n_in,
                              void* d_out, int out_size)
{
    const float* iQ = (const float*)d_in[0];
    const float* iK = (const float*)d_in[1];
    const float* iV = (const float*)d_in[2];
    const void*  mask = d_in[3];
    const float* Wq = (const float*)d_in[4];
    const float* bq = (const float*)d_in[5];
    const float* Wk = (const float*)d_in[6];
    const float* bk = (const float*)d_in[7];
    const float* Wv = (const float*)d_in[8];
    const float* bv = (const float*)d_in[9];
    float* out = (float*)d_out;

    // >48KB dynamic smem opt-in (capture-safe: no allocation, no stream sync)
    cudaFuncSetAttribute(attn_kernel, cudaFuncAttributeMaxDynamicSharedMemorySize,
                         (int)sizeof(AttnSmem));

    detect_mask_kernel<<<1, 32>>>((const unsigned int*)mask);

    dim3 pgrid(BSROWS / 64, 3);
    proj_kernel<<<pgrid, 256>>>(iQ, iK, iV, Wq, Wk, Wv, bq, bk, bv);

    dim3 agrid(SS / 64, BB);
    attn_kernel<<<agrid, 256, sizeof(AttnSmem)>>>(mask, out);
}